// round 12
// baseline (speedup 1.0000x reference)
#include <cuda_runtime.h>
#include <math.h>

#define NTOK 2048
#define NH   8
#define NN   32
#define NJ   34

#define SCALE0  0.25f
#define SCALE1  0.14433756729740643f
#define SHAREDC 0.70710678118654752f
#define NEGV    -1e9f

typedef unsigned long long ull;

// ---------------- scratch ----------------
__device__ float g_skv0[NTOK * 256];       // [0..128)=k_self, [128..256)=v_self
__device__ float g_skv1[NTOK * 768];       // (i, o, m): o<128 k, o>=128 v
__device__ float g_out0[NTOK * 128];
__device__ float g_out1[NTOK * 384];       // (i, c, m)
__device__ float g_attn[NTOK * 288];       // per token: [NH][NJ] weights (272 used)
__device__ int   g_mask_mode;              // 0=byte, 1=int32, 2=float32

__device__ __forceinline__ float dot4(float4 a, float4 b) {
    return a.x*b.x + a.y*b.y + a.z*b.z + a.w*b.w;
}
__device__ __forceinline__ void ffma2(ull& d, ull a, ull b) {
    asm("fma.rn.f32x2 %0, %1, %2, %0;" : "+l"(d) : "l"(a), "l"(b));
}

// ------- f32x2 tiled SGEMM (C = A * B^T): 128 thr, BM=64 x BN=32, 4m x 4n/thr -------
#define BM 64
#define BN 32
#define BK 16
#define ALD (BM + 4)        // 68 floats = 272B, 16B-multiple
#define BLD (2 * BN + 8)    // 72 floats = 288B, 16B-multiple

template<int K>
__device__ __forceinline__ void gemm_body(
    const float* __restrict__ A, const float* __restrict__ B, float* __restrict__ C,
    int lda, int eA, int ldc, int eC, int m0, int n0,
    float (*As)[BK][ALD], float (*Bs)[BK][BLD])
{
    const int t  = threadIdx.x;      // 0..127
    const int tx = t & 7;            // n quad
    const int ty = t >> 3;           // m quad (0..15)
    const int aK = t & 15;
    const int aM = t >> 4;           // 0..7

    ull acc[2][4];                   // [m-pair][n]
    #pragma unroll
    for (int r = 0; r < 2; r++)
        #pragma unroll
        for (int s = 0; s < 4; s++) acc[r][s] = 0ull;

    float ra[8], rb[4];
    #pragma unroll
    for (int r = 0; r < 8; r++)
        ra[r] = A[(size_t)(m0 + aM + 8*r) * lda + (size_t)aK * eA];
    #pragma unroll
    for (int r = 0; r < 4; r++)
        rb[r] = B[(size_t)(n0 + aM + 8*r) * K + aK];

    int buf = 0;
    #pragma unroll
    for (int k0 = 0; k0 < K; k0 += BK) {
        #pragma unroll
        for (int r = 0; r < 8; r++) As[buf][aK][aM + 8*r] = ra[r];
        #pragma unroll
        for (int r = 0; r < 4; r++) {
            float2 d = make_float2(rb[r], rb[r]);
            *(float2*)&Bs[buf][aK][2 * (aM + 8*r)] = d;   // duplicated pairs
        }
        __syncthreads();
        const int kn = k0 + BK;
        if (kn < K) {
            #pragma unroll
            for (int r = 0; r < 8; r++)
                ra[r] = A[(size_t)(m0 + aM + 8*r) * lda + (size_t)(kn + aK) * eA];
            #pragma unroll
            for (int r = 0; r < 4; r++)
                rb[r] = B[(size_t)(n0 + aM + 8*r) * K + (kn + aK)];
        }
        #pragma unroll
        for (int kk = 0; kk < BK; kk++) {
            ulonglong2 ap  = *(const ulonglong2*)&As[buf][kk][ty * 4];      // 2 m-pairs
            ulonglong2 b01 = *(const ulonglong2*)&Bs[buf][kk][tx * 8];      // n, n+1 dup
            ulonglong2 b23 = *(const ulonglong2*)&Bs[buf][kk][tx * 8 + 4];  // n+2, n+3
            ffma2(acc[0][0], ap.x, b01.x); ffma2(acc[0][1], ap.x, b01.y);
            ffma2(acc[0][2], ap.x, b23.x); ffma2(acc[0][3], ap.x, b23.y);
            ffma2(acc[1][0], ap.y, b01.x); ffma2(acc[1][1], ap.y, b01.y);
            ffma2(acc[1][2], ap.y, b23.x); ffma2(acc[1][3], ap.y, b23.y);
        }
        buf ^= 1;
        if (kn < K) __syncthreads();
    }
    #pragma unroll
    for (int r = 0; r < 2; r++)
        #pragma unroll
        for (int s = 0; s < 4; s++) {
            float2 v = *(float2*)&acc[r][s];
            size_t nidx = (size_t)(n0 + tx*4 + s) * eC;
            C[(size_t)(m0 + ty*4 + 2*r)     * ldc + nidx] = v.x;
            C[(size_t)(m0 + ty*4 + 2*r + 1) * ldc + nidx] = v.y;
        }
}

// z==0: deg0 self-kv (K=128); z in 1..3: deg1 slice z-1 (K=64). Embeds mask detect.
__global__ __launch_bounds__(128, 8) void skv_fused_kernel(
    const float* __restrict__ feats0, const float* __restrict__ Wskv0,
    const float* __restrict__ feats1, const float* __restrict__ Wskv1,
    const unsigned int* __restrict__ mask)
{
    if (blockIdx.z == 0 && blockIdx.x == 0 && blockIdx.y == 0 && threadIdx.x == 0) {
        int allBin = 1, allFloat = 1;
        for (int k = 0; k < 128; k++) {
            unsigned v = mask[k];
            if (v != 0u && v != 1u) allBin = 0;
            if (v != 0u && v != 0x3F800000u) allFloat = 0;
        }
        g_mask_mode = allBin ? 1 : (allFloat ? 2 : 0);
    }
    __shared__ __align__(16) float As[2][BK][ALD];
    __shared__ __align__(16) float Bs[2][BK][BLD];
    const int m0 = blockIdx.y * BM, n0 = blockIdx.x * BN;
    if (blockIdx.z == 0) {
        gemm_body<128>(feats0, Wskv0, g_skv0, 128, 1, 256, 1, m0, n0, As, Bs);
    } else {
        int m = blockIdx.z - 1;
        gemm_body<64>(feats1 + m, Wskv1, g_skv1 + m, 192, 3, 768, 3, m0, n0, As, Bs);
    }
}

// z==0: y0 (x=0..3); z in 1..3: y1 slice (x<2)
__global__ __launch_bounds__(128, 8) void out_fused_kernel(
    const float* __restrict__ Wout0, const float* __restrict__ Wout1,
    float* __restrict__ out)
{
    if (blockIdx.z != 0 && blockIdx.x >= 2) return;
    __shared__ __align__(16) float As[2][BK][ALD];
    __shared__ __align__(16) float Bs[2][BK][BLD];
    const int m0 = blockIdx.y * BM, n0 = blockIdx.x * BN;
    if (blockIdx.z == 0) {
        gemm_body<128>(g_out0, Wout0, out, 128, 1, 128, 1, m0, n0, As, Bs);
    } else {
        int m = blockIdx.z - 1;
        gemm_body<128>(g_out1 + m, Wout1, out + (size_t)NTOK * 128 + m,
                       384, 3, 192, 3, m0, n0, As, Bs);
    }
}

// ---------------- logits + softmax: one token per 256-thread block ----------------
__global__ __launch_bounds__(256) void logits_kernel(
    const float* __restrict__ q0, const float* __restrict__ q1,
    const float* __restrict__ k0, const float* __restrict__ k1,
    const float* __restrict__ edges, const float* __restrict__ wbias,
    const float* __restrict__ self_bias, const float* __restrict__ null_bias,
    const float* __restrict__ nk0, const float* __restrict__ nk1,
    const float* __restrict__ hw1, const void* __restrict__ nbmask)
{
    const int i = blockIdx.x;
    const int t = threadIdx.x;

    __shared__ __align__(16) float q0s[128];   // pre-scaled
    __shared__ __align__(16) float q1s[384];   // pre-scaled
    __shared__ __align__(16) float wb[256];    // pre-scaled
    __shared__ float sbS[NH], nbS[NH];
    __shared__ float totS[NH * NJ];
    __shared__ float attnS[NH * NJ];
    __shared__ int validS[NJ];

    // ---- stage ----
    if (t < 128) {
        q0s[t] = q0[(size_t)i * 128 + t] * (SCALE0 * SHAREDC);
        wb[t]       = wbias[t] * SHAREDC;
        wb[t + 128] = wbias[t + 128] * SHAREDC;
    } else {
        int o = t - 128;                 // 0..127
        #pragma unroll
        for (int rep = 0; rep < 3; rep++) {
            int oo = o + rep * 128;
            int h = oo / 48;
            float x = hw1[h];
            float sp = (x > 20.f) ? x : log1pf(__expf(x));
            q1s[oo] = q1[(size_t)i * 384 + oo] * (sp * SCALE1 * SHAREDC);
        }
    }
    if (t >= 128 && t < 128 + NJ) {
        int j = t - 128;
        if (j < 2) {
            validS[j] = 1;
        } else {
            int mm = g_mask_mode;
            int mi = i * NN + (j - 2);
            int valid;
            if (mm == 1)      valid = ((const int*)nbmask)[mi] != 0;
            else if (mm == 2) valid = ((const float*)nbmask)[mi] != 0.f;
            else              valid = ((const unsigned char*)nbmask)[mi] != 0;
            validS[j] = valid;
        }
    }
    if (t >= 168 && t < 176) {
        int h = t - 168;
        sbS[h] = self_bias[h] * SHAREDC;
        nbS[h] = null_bias[h] * SHAREDC;
    }
    __syncthreads();

    // ---- logits: warp per j; compile-time unrolled for load batching ----
    {
        const int w = t >> 5, lane = t & 31;
        const int h = lane >> 2, part = lane & 3;
        const float4 qa = ((const float4*)q0s)[lane];
        const float4* q1v = (const float4*)(q1s + 12 * lane);
        const float4 qb0 = q1v[0], qb1 = q1v[1], qb2 = q1v[2];

        // j = 2 + w + 8*it, it = 0..3  -> covers j = 2..33 exactly
        #pragma unroll 2
        for (int it = 0; it < 4; it++) {
            const int j = 2 + w + 8 * it;
            const size_t r = (size_t)i * NN + (j - 2);
            const float4* k0p = (const float4*)(k0 + r * 128);
            const float4* k1p = (const float4*)(k1 + r * 384 + 12 * lane);
            float4 ka  = k0p[lane];
            float4 kb0 = k1p[0], kb1 = k1p[1], kb2 = k1p[2];
            const float4* ep  = (const float4*)(edges + (size_t)i * 1024 + (j - 2) * 32 + part * 8);
            float4 e0 = ep[0], e1 = ep[1];
            const float4* wbp = (const float4*)(wb + h * 32 + part * 8);
            float p = dot4(qa, ka) + dot4(qb0, kb0) + dot4(qb1, kb1) + dot4(qb2, kb2)
                    + dot4(e0, wbp[0]) + dot4(e1, wbp[1]);
            p += __shfl_down_sync(0xffffffffu, p, 2);
            p += __shfl_down_sync(0xffffffffu, p, 1);
            if (part == 0)
                totS[h * NJ + j] = validS[j] ? p : NEGV;
        }

        // j = 0 (null) on warp 0, j = 1 (self) on warp 1
        if (w < 2) {
            const float* kp0 = (w == 0) ? nk0 : g_skv0 + (size_t)i * 256;
            const float* kp1 = (w == 0) ? nk1 : g_skv1 + (size_t)i * 768;
            float4 ka  = ((const float4*)kp0)[lane];
            const float4* k1p = (const float4*)(kp1 + 12 * lane);
            float4 kb0 = k1p[0], kb1 = k1p[1], kb2 = k1p[2];
            float p = dot4(qa, ka) + dot4(qb0, kb0) + dot4(qb1, kb1) + dot4(qb2, kb2);
            p += __shfl_down_sync(0xffffffffu, p, 2);
            p += __shfl_down_sync(0xffffffffu, p, 1);
            if (part == 0) {
                p += (w == 0) ? nbS[h] : sbS[h];
                totS[h * NJ + w] = p;
            }
        }
    }
    __syncthreads();

    // ---- softmax: warp w = head w ----
    {
        const int w = t >> 5, lane = t & 31;
        float x1 = totS[w * NJ + lane];
        float x2 = (lane < 2) ? totS[w * NJ + 32 + lane] : -2e9f;
        float mx = fmaxf(x1, x2);
        #pragma unroll
        for (int o = 16; o > 0; o >>= 1) mx = fmaxf(mx, __shfl_xor_sync(0xffffffffu, mx, o));
        float e1 = __expf(x1 - mx);
        float e2 = (lane < 2) ? __expf(x2 - mx) : 0.f;
        float s = e1 + e2;
        #pragma unroll
        for (int o = 16; o > 0; o >>= 1) s += __shfl_xor_sync(0xffffffffu, s, o);
        float inv = 1.f / s;
        attnS[w * NJ + lane] = e1 * inv;
        if (lane < 2) attnS[w * NJ + 32 + lane] = e2 * inv;
    }
    __syncthreads();
    for (int l = t; l < NH * NJ; l += 256)
        g_attn[(size_t)i * 288 + l] = attnS[l];
}

// ---------------- V accumulation: one token per 256-thread block ----------------
__global__ __launch_bounds__(256, 4) void vaccum_kernel(
    const float* __restrict__ v0, const float* __restrict__ v1,
    const float* __restrict__ nv0, const float* __restrict__ nv1)
{
    const int i = blockIdx.x;
    const int t = threadIdx.x;

    __shared__ float aS[NH * NJ];
    __shared__ __align__(16) float red[512];

    for (int l = t; l < NH * NJ; l += 256)
        aS[l] = g_attn[(size_t)i * 288 + l];
    __syncthreads();

    const int g  = t >> 7;        // 0: j 0,1,2..17 ; 1: j 18..33
    const int tl = t & 127;
    const bool isV1 = (tl < 96);
    const int off = isV1 ? 4 * tl : 4 * (tl - 96);
    const int hv  = isV1 ? (tl / 12) : ((tl - 96) / 4);
    const float* vb = isV1 ? v1 : v0;
    const int stride = isV1 ? 384 : 128;

    float4 acc = make_float4(0.f, 0.f, 0.f, 0.f);
    if (g == 0) {
        const float* np = (isV1 ? nv1 : nv0) + off;
        const float* sp = (isV1 ? g_skv1 + (size_t)i * 768 + 384
                                : g_skv0 + (size_t)i * 256 + 128) + off;
        float4 vn = *(const float4*)np;
        float4 vs = *(const float4*)sp;
        float w0 = aS[hv * NJ + 0], w1 = aS[hv * NJ + 1];
        acc.x = w0 * vn.x + w1 * vs.x;
        acc.y = w0 * vn.y + w1 * vs.y;
        acc.z = w0 * vn.z + w1 * vs.z;
        acc.w = w0 * vn.w + w1 * vs.w;
    }
    // affine, compile-time 16-iteration loop -> ptxas batches independent loads
    const float* vrow = vb + ((size_t)i * NN + (g ? 16 : 0)) * stride + off;
    const int jbase = g ? 18 : 2;
    #pragma unroll
    for (int jj = 0; jj < 16; jj++) {
        float wgt = aS[hv * NJ + jbase + jj];
        float4 v = *(const float4*)(vrow + (size_t)jj * stride);
        acc.x = fmaf(wgt, v.x, acc.x);
        acc.y = fmaf(wgt, v.y, acc.y);
        acc.z = fmaf(wgt, v.z, acc.z);
        acc.w = fmaf(wgt, v.w, acc.w);
    }
    if (g == 1) ((float4*)red)[tl] = acc;
    __syncthreads();
    if (g == 0) {
        float4 o = ((const float4*)red)[tl];
        acc.x += o.x; acc.y += o.y; acc.z += o.z; acc.w += o.w;
        if (isV1) *(float4*)(g_out1 + (size_t)i * 384 + off) = acc;
        else      *(float4*)(g_out0 + (size_t)i * 128 + off) = acc;
    }
}

// ---------------- launch ----------------
extern "C" void kernel_launch(void* const* d_in, const int* in_sizes, int n_in,
                              void* d_out, int out_size)
{
    const float* q0     = (const float*)d_in[0];
    const float* k0     = (const float*)d_in[1];
    const float* v0     = (const float*)d_in[2];
    const float* q1     = (const float*)d_in[3];
    const float* k1     = (const float*)d_in[4];
    const float* v1     = (const float*)d_in[5];
    const float* feats0 = (const float*)d_in[6];
    const float* feats1 = (const float*)d_in[7];
    const float* edges  = (const float*)d_in[8];
    const float* Wskv0  = (const float*)d_in[9];
    const float* Wskv1  = (const float*)d_in[10];
    const float* Wbias  = (const float*)d_in[11];
    const float* sbias  = (const float*)d_in[12];
    const float* nbias  = (const float*)d_in[13];
    const float* nk0    = (const float*)d_in[14];
    const float* nv0    = (const float*)d_in[15];
    const float* nk1    = (const float*)d_in[16];
    const float* nv1    = (const float*)d_in[17];
    const float* hw1    = (const float*)d_in[18];
    const float* Wout0  = (const float*)d_in[19];
    const float* Wout1  = (const float*)d_in[20];
    const void*  nbm    = d_in[21];
    float* out = (float*)d_out;

    skv_fused_kernel<<<dim3(256 / BN, NTOK / BM, 4), 128>>>(
        feats0, Wskv0, feats1, Wskv1, (const unsigned int*)nbm);

    logits_kernel<<<NTOK, 256>>>(q0, q1, k0, k1, edges, Wbias,
                                 sbias, nbias, nk0, nk1, hw1, nbm);

    vaccum_kernel<<<NTOK, 256>>>(v0, v1, nv0, nv1);

    out_fused_kernel<<<dim3(128 / BN, NTOK / BM, 4), 128>>>(Wout0, Wout1, out);
}

// round 13
// speedup vs baseline: 1.2928x; 1.2928x over previous
#include <cuda_runtime.h>
#include <math.h>

#define NTOK 2048
#define NH   8
#define NN   32
#define NJ   34

#define SCALE0  0.25f
#define SCALE1  0.14433756729740643f
#define SHAREDC 0.70710678118654752f
#define NEGV    -1e9f

// ---------------- scratch ----------------
__device__ float g_skv0[NTOK * 256];       // [0..128)=k_self, [128..256)=v_self
__device__ float g_skv1[NTOK * 768];       // (i, o, m): o<128 k, o>=128 v
__device__ float g_out0[NTOK * 128];
__device__ float g_out1[NTOK * 384];       // (i, c, m)
__device__ float g_attn[NTOK * 288];       // per token: [NH][NJ] weights (272 used)
__device__ int   g_mask_mode;              // 0=byte, 1=int32, 2=float32

__device__ __forceinline__ float dot4(float4 a, float4 b) {
    return a.x*b.x + a.y*b.y + a.z*b.z + a.w*b.w;
}

// ------- FFMA tiled SGEMM (C = A * B^T): 128 lanes, BM=32 x BN=32, BK=16 -------
#define BK  16
#define GLD 36    // 32 + 4 pad; rows are 144B (16B multiple)

struct GemSm { float As[2][BK][GLD]; float Bs[2][BK][GLD]; };

template<int K>
__device__ __forceinline__ void gemm32(
    const float* __restrict__ A, const float* __restrict__ B, float* __restrict__ C,
    int lda, int eA, int ldc, int eC, int m0, int n0, int tl, GemSm* sm)
{
    const int tx = tl & 7;           // n quad
    const int ty = tl >> 3;          // m pair (0..15)
    const int aK = tl & 15;
    const int aM = tl >> 4;          // 0..7

    float acc[2][4] = {};
    float ra[4], rb[4];

    #pragma unroll
    for (int r = 0; r < 4; r++) {
        ra[r] = A[(size_t)(m0 + aM + 8*r) * lda + (size_t)aK * eA];
        rb[r] = B[(size_t)(n0 + aM + 8*r) * K + aK];
    }

    int buf = 0;
    #pragma unroll
    for (int k0 = 0; k0 < K; k0 += BK) {
        #pragma unroll
        for (int r = 0; r < 4; r++) {
            sm->As[buf][aK][aM + 8*r] = ra[r];
            sm->Bs[buf][aK][aM + 8*r] = rb[r];
        }
        __syncthreads();
        const int kn = k0 + BK;
        if (kn < K) {
            #pragma unroll
            for (int r = 0; r < 4; r++) {
                ra[r] = A[(size_t)(m0 + aM + 8*r) * lda + (size_t)(kn + aK) * eA];
                rb[r] = B[(size_t)(n0 + aM + 8*r) * K + (kn + aK)];
            }
        }
        #pragma unroll
        for (int kk = 0; kk < BK; kk++) {
            float2 a = *(const float2*)&sm->As[buf][kk][ty * 2];
            float4 b = *(const float4*)&sm->Bs[buf][kk][tx * 4];
            float bv[4] = {b.x, b.y, b.z, b.w};
            #pragma unroll
            for (int s = 0; s < 4; s++) {
                acc[0][s] = fmaf(a.x, bv[s], acc[0][s]);
                acc[1][s] = fmaf(a.y, bv[s], acc[1][s]);
            }
        }
        buf ^= 1;
        if (kn < K) __syncthreads();
    }
    #pragma unroll
    for (int r = 0; r < 2; r++)
        #pragma unroll
        for (int s = 0; s < 4; s++)
            C[(size_t)(m0 + ty*2 + r) * ldc + (size_t)(n0 + tx*4 + s) * eC] = acc[r][s];
}

// ---------------- self-K projection (+mask detect): grid (4, 64, 4), 128 thr ----------------
__global__ __launch_bounds__(128) void skv_k_kernel(
    const float* __restrict__ feats0, const float* __restrict__ Wskv0,
    const float* __restrict__ feats1, const float* __restrict__ Wskv1,
    const unsigned int* __restrict__ mask)
{
    if (blockIdx.z == 0 && blockIdx.x == 0 && blockIdx.y == 0 && threadIdx.x == 0) {
        int allBin = 1, allFloat = 1;
        for (int k = 0; k < 128; k++) {
            unsigned v = mask[k];
            if (v != 0u && v != 1u) allBin = 0;
            if (v != 0u && v != 0x3F800000u) allFloat = 0;
        }
        g_mask_mode = allBin ? 1 : (allFloat ? 2 : 0);
    }
    __shared__ __align__(16) GemSm sm;
    const int m0 = blockIdx.y * 32, n0 = blockIdx.x * 32;   // K half: cols 0..127
    if (blockIdx.z == 0) {
        gemm32<128>(feats0, Wskv0, g_skv0, 128, 1, 256, 1, m0, n0, threadIdx.x, &sm);
    } else {
        int m = blockIdx.z - 1;
        gemm32<64>(feats1 + m, Wskv1, g_skv1 + m, 192, 3, 768, 3, m0, n0, threadIdx.x, &sm);
    }
}

// ---------------- output projection: grid (4, 64, 4), 128 thr ----------------
__global__ __launch_bounds__(128) void out_fused_kernel(
    const float* __restrict__ Wout0, const float* __restrict__ Wout1,
    float* __restrict__ out)
{
    if (blockIdx.z != 0 && blockIdx.x >= 2) return;
    __shared__ __align__(16) GemSm sm;
    const int m0 = blockIdx.y * 32, n0 = blockIdx.x * 32;
    if (blockIdx.z == 0) {
        gemm32<128>(g_out0, Wout0, out, 128, 1, 128, 1, m0, n0, threadIdx.x, &sm);
    } else {
        int m = blockIdx.z - 1;
        gemm32<128>(g_out1 + m, Wout1, out + (size_t)NTOK * 128 + m,
                    384, 3, 192, 3, m0, n0, threadIdx.x, &sm);
    }
}

// ---------------- logits + softmax + ride-along self-V GEMM ----------------
// grid: 512 ride blocks (bid < 512, 2 V-tiles each) then NTOK logits blocks. 256 thr.
#define RIDE_BLOCKS 512

struct LogSm {
    float q0s[128]; float q1s[384]; float wb[256];
    float sbS[NH], nbS[NH];
    float totS[NH * NJ]; float attnS[NH * NJ];
    int validS[NJ];
};
union USm { LogSm l; GemSm g[2]; };

__global__ __launch_bounds__(256) void logits_kernel(
    const float* __restrict__ q0, const float* __restrict__ q1,
    const float* __restrict__ k0, const float* __restrict__ k1,
    const float* __restrict__ edges, const float* __restrict__ wbias,
    const float* __restrict__ self_bias, const float* __restrict__ null_bias,
    const float* __restrict__ nk0, const float* __restrict__ nk1,
    const float* __restrict__ hw1, const void* __restrict__ nbmask,
    const float* __restrict__ feats0, const float* __restrict__ Wskv0,
    const float* __restrict__ feats1, const float* __restrict__ Wskv1)
{
    __shared__ __align__(16) USm sm;
    const int t = threadIdx.x;

    if (blockIdx.x < RIDE_BLOCKS) {
        // ---- self-V GEMM tiles: tile = 2*bid + (t>>7); V half: n0 = 128 + 32x ----
        const int tile = 2 * blockIdx.x + (t >> 7);
        const int tl   = t & 127;
        const int z    = tile >> 8;          // 256 tiles per z
        const int rem  = tile & 255;
        const int y    = rem >> 2, x = rem & 3;
        const int m0 = 32 * y, n0 = 128 + 32 * x;
        GemSm* gs = &sm.g[t >> 7];
        if (z == 0) {
            gemm32<128>(feats0, Wskv0, g_skv0, 128, 1, 256, 1, m0, n0, tl, gs);
        } else {
            int m = z - 1;
            gemm32<64>(feats1 + m, Wskv1, g_skv1 + m, 192, 3, 768, 3, m0, n0, tl, gs);
        }
        return;
    }

    const int i = blockIdx.x - RIDE_BLOCKS;

    // ---- stage ----
    if (t < 128) {
        sm.l.q0s[t] = q0[(size_t)i * 128 + t] * (SCALE0 * SHAREDC);
        sm.l.wb[t]       = wbias[t] * SHAREDC;
        sm.l.wb[t + 128] = wbias[t + 128] * SHAREDC;
    } else {
        int o = t - 128;                 // 0..127
        #pragma unroll
        for (int rep = 0; rep < 3; rep++) {
            int oo = o + rep * 128;
            int h = oo / 48;
            float x = hw1[h];
            float sp = (x > 20.f) ? x : log1pf(__expf(x));
            sm.l.q1s[oo] = q1[(size_t)i * 384 + oo] * (sp * SCALE1 * SHAREDC);
        }
    }
    if (t >= 128 && t < 128 + NJ) {
        int j = t - 128;
        if (j < 2) {
            sm.l.validS[j] = 1;
        } else {
            int mm = g_mask_mode;
            int mi = i * NN + (j - 2);
            int valid;
            if (mm == 1)      valid = ((const int*)nbmask)[mi] != 0;
            else if (mm == 2) valid = ((const float*)nbmask)[mi] != 0.f;
            else              valid = ((const unsigned char*)nbmask)[mi] != 0;
            sm.l.validS[j] = valid;
        }
    }
    if (t >= 168 && t < 176) {
        int h = t - 168;
        sm.l.sbS[h] = self_bias[h] * SHAREDC;
        sm.l.nbS[h] = null_bias[h] * SHAREDC;
    }
    __syncthreads();

    // ---- logits: warp per j; compile-time unrolled ----
    {
        const int w = t >> 5, lane = t & 31;
        const int h = lane >> 2, part = lane & 3;
        const float4 qa = ((const float4*)sm.l.q0s)[lane];
        const float4* q1v = (const float4*)(sm.l.q1s + 12 * lane);
        const float4 qb0 = q1v[0], qb1 = q1v[1], qb2 = q1v[2];

        #pragma unroll 2
        for (int it = 0; it < 4; it++) {
            const int j = 2 + w + 8 * it;
            const size_t r = (size_t)i * NN + (j - 2);
            const float4* k0p = (const float4*)(k0 + r * 128);
            const float4* k1p = (const float4*)(k1 + r * 384 + 12 * lane);
            float4 ka  = k0p[lane];
            float4 kb0 = k1p[0], kb1 = k1p[1], kb2 = k1p[2];
            const float4* ep  = (const float4*)(edges + (size_t)i * 1024 + (j - 2) * 32 + part * 8);
            float4 e0 = ep[0], e1 = ep[1];
            const float4* wbp = (const float4*)(sm.l.wb + h * 32 + part * 8);
            float p = dot4(qa, ka) + dot4(qb0, kb0) + dot4(qb1, kb1) + dot4(qb2, kb2)
                    + dot4(e0, wbp[0]) + dot4(e1, wbp[1]);
            p += __shfl_down_sync(0xffffffffu, p, 2);
            p += __shfl_down_sync(0xffffffffu, p, 1);
            if (part == 0)
                sm.l.totS[h * NJ + j] = sm.l.validS[j] ? p : NEGV;
        }

        if (w < 2) {
            const float* kp0 = (w == 0) ? nk0 : g_skv0 + (size_t)i * 256;
            const float* kp1 = (w == 0) ? nk1 : g_skv1 + (size_t)i * 768;
            float4 ka  = ((const float4*)kp0)[lane];
            const float4* k1p = (const float4*)(kp1 + 12 * lane);
            float4 kb0 = k1p[0], kb1 = k1p[1], kb2 = k1p[2];
            float p = dot4(qa, ka) + dot4(qb0, kb0) + dot4(qb1, kb1) + dot4(qb2, kb2);
            p += __shfl_down_sync(0xffffffffu, p, 2);
            p += __shfl_down_sync(0xffffffffu, p, 1);
            if (part == 0) {
                p += (w == 0) ? sm.l.nbS[h] : sm.l.sbS[h];
                sm.l.totS[h * NJ + w] = p;
            }
        }
    }
    __syncthreads();

    // ---- softmax: warp w = head w ----
    {
        const int w = t >> 5, lane = t & 31;
        float x1 = sm.l.totS[w * NJ + lane];
        float x2 = (lane < 2) ? sm.l.totS[w * NJ + 32 + lane] : -2e9f;
        float mx = fmaxf(x1, x2);
        #pragma unroll
        for (int o = 16; o > 0; o >>= 1) mx = fmaxf(mx, __shfl_xor_sync(0xffffffffu, mx, o));
        float e1 = __expf(x1 - mx);
        float e2 = (lane < 2) ? __expf(x2 - mx) : 0.f;
        float s = e1 + e2;
        #pragma unroll
        for (int o = 16; o > 0; o >>= 1) s += __shfl_xor_sync(0xffffffffu, s, o);
        float inv = 1.f / s;
        sm.l.attnS[w * NJ + lane] = e1 * inv;
        if (lane < 2) sm.l.attnS[w * NJ + 32 + lane] = e2 * inv;
    }
    __syncthreads();
    for (int l = t; l < NH * NJ; l += 256)
        g_attn[(size_t)i * 288 + l] = sm.l.attnS[l];
}

// ---------------- V accumulation: one token per 256-thread block ----------------
__global__ __launch_bounds__(256) void vaccum_kernel(
    const float* __restrict__ v0, const float* __restrict__ v1,
    const float* __restrict__ nv0, const float* __restrict__ nv1)
{
    const int i = blockIdx.x;
    const int t = threadIdx.x;

    __shared__ float aS[NH * NJ];
    __shared__ __align__(16) float red[512];

    for (int l = t; l < NH * NJ; l += 256)
        aS[l] = g_attn[(size_t)i * 288 + l];
    __syncthreads();

    const int g  = t >> 7;        // 0: j 0,1,2..17 ; 1: j 18..33
    const int tl = t & 127;
    const bool isV1 = (tl < 96);
    const int off = isV1 ? 4 * tl : 4 * (tl - 96);
    const int hv  = isV1 ? (tl / 12) : ((tl - 96) / 4);
    const float* vb = isV1 ? v1 : v0;
    const int stride = isV1 ? 384 : 128;

    float4 acc = make_float4(0.f, 0.f, 0.f, 0.f);
    if (g == 0) {
        const float* np = (isV1 ? nv1 : nv0) + off;
        const float* sp = (isV1 ? g_skv1 + (size_t)i * 768 + 384
                                : g_skv0 + (size_t)i * 256 + 128) + off;
        float4 vn = *(const float4*)np;
        float4 vs = *(const float4*)sp;
        float w0 = aS[hv * NJ + 0], w1 = aS[hv * NJ + 1];
        acc.x = w0 * vn.x + w1 * vs.x;
        acc.y = w0 * vn.y + w1 * vs.y;
        acc.z = w0 * vn.z + w1 * vs.z;
        acc.w = w0 * vn.w + w1 * vs.w;
    }
    const float* vrow = vb + ((size_t)i * NN + (g ? 16 : 0)) * stride + off;
    const int jbase = g ? 18 : 2;
    #pragma unroll
    for (int jj = 0; jj < 16; jj++) {
        float wgt = aS[hv * NJ + jbase + jj];
        float4 v = *(const float4*)(vrow + (size_t)jj * stride);
        acc.x = fmaf(wgt, v.x, acc.x);
        acc.y = fmaf(wgt, v.y, acc.y);
        acc.z = fmaf(wgt, v.z, acc.z);
        acc.w = fmaf(wgt, v.w, acc.w);
    }
    if (g == 1) ((float4*)red)[tl] = acc;
    __syncthreads();
    if (g == 0) {
        float4 o = ((const float4*)red)[tl];
        acc.x += o.x; acc.y += o.y; acc.z += o.z; acc.w += o.w;
        if (isV1) *(float4*)(g_out1 + (size_t)i * 384 + off) = acc;
        else      *(float4*)(g_out0 + (size_t)i * 128 + off) = acc;
    }
}

// ---------------- launch ----------------
extern "C" void kernel_launch(void* const* d_in, const int* in_sizes, int n_in,
                              void* d_out, int out_size)
{
    const float* q0     = (const float*)d_in[0];
    const float* k0     = (const float*)d_in[1];
    const float* v0     = (const float*)d_in[2];
    const float* q1     = (const float*)d_in[3];
    const float* k1     = (const float*)d_in[4];
    const float* v1     = (const float*)d_in[5];
    const float* feats0 = (const float*)d_in[6];
    const float* feats1 = (const float*)d_in[7];
    const float* edges  = (const float*)d_in[8];
    const float* Wskv0  = (const float*)d_in[9];
    const float* Wskv1  = (const float*)d_in[10];
    const float* Wbias  = (const float*)d_in[11];
    const float* sbias  = (const float*)d_in[12];
    const float* nbias  = (const float*)d_in[13];
    const float* nk0    = (const float*)d_in[14];
    const float* nv0    = (const float*)d_in[15];
    const float* nk1    = (const float*)d_in[16];
    const float* nv1    = (const float*)d_in[17];
    const float* hw1    = (const float*)d_in[18];
    const float* Wout0  = (const float*)d_in[19];
    const float* Wout1  = (const float*)d_in[20];
    const void*  nbm    = d_in[21];
    float* out = (float*)d_out;

    // self-K projection (half the skv GEMM) + mask detect
    skv_k_kernel<<<dim3(4, 64, 4), 128>>>(
        feats0, Wskv0, feats1, Wskv1, (const unsigned int*)nbm);

    // logits + softmax, with self-V GEMM tiles riding along as the first 512 blocks
    logits_kernel<<<RIDE_BLOCKS + NTOK, 256>>>(
        q0, q1, k0, k1, edges, Wbias, sbias, nbias, nk0, nk1, hw1, nbm,
        feats0, Wskv0, feats1, Wskv1);

    vaccum_kernel<<<NTOK, 256>>>(v0, v1, nv0, nv1);

    out_fused_kernel<<<dim3(4, 64, 4), 128>>>(Wout0, Wout1, out);
}